// round 1
// baseline (speedup 1.0000x reference)
#include <cuda_runtime.h>

// Problem constants
#define R_TOTAL 16384   // B*L = 16*1024 rows
#define KDIM    1024    // D
#define NDEP    500     // MLP_DIM
#define NTOT    1000    // both branches concatenated along N
#define NEG_SLOPE 0.01f

// GEMM tiling
#define BM 64
#define BN 64
#define BK 16
#define TM 4
#define TN 4
#define PAD 4           // smem row padding (keeps 16B alignment, breaks conflicts)

// Scratch: per-row scores. Layout [row][4] = {dep_c0, dep_c1, head_c0, head_c1}
__device__ float g_scores[R_TOTAL * 4];

// ---------------------------------------------------------------------------
// Kernel 1: fused  scores = leaky(A @ [W_dep|W_head] + b) @ Wc
// Grid: R_TOTAL/BM blocks, 256 threads. Each block owns BM rows and loops the
// full N=1000 so it produces final (un-reduced-across-blocks) scores -> no
// global atomics needed.
// ---------------------------------------------------------------------------
__global__ __launch_bounds__(256) void gemm_scores_kernel(
    const float* __restrict__ A,    // [R, K] row-major
    const float* __restrict__ Wd,   // [K, 500] row-major
    const float* __restrict__ bd,   // [500]
    const float* __restrict__ Wh,   // [K, 500]
    const float* __restrict__ bh,   // [500]
    const float* __restrict__ Wc)   // [1000, 2]
{
    __shared__ float As[BK][BM + PAD];  // A tile, transposed: As[k][m]
    __shared__ float Ws[BK][BN + PAD];  // W tile: Ws[k][n]

    const int tid  = threadIdx.x;
    const int tx   = tid & 15;   // col group (owns cols tx*4 .. tx*4+3)
    const int ty   = tid >> 4;   // row group (owns rows ty*4 .. ty*4+3)
    const int row0 = blockIdx.x * BM;

    // A-tile load mapping: thread -> row a_r, k-segment a_k (float4)
    const int a_r = tid >> 2;          // 0..63
    const int a_k = (tid & 3) * 4;     // 0,4,8,12

    // W-tile load mapping: thread -> k-row w_d, n-segment w_n
    const int w_d = tid >> 4;          // 0..15
    const int w_n = (tid & 15) * 4;    // 0..60

    float pscore[TM][4];
    #pragma unroll
    for (int r = 0; r < TM; r++)
        #pragma unroll
        for (int c = 0; c < 4; c++) pscore[r][c] = 0.f;

    for (int n0 = 0; n0 < NTOT; n0 += BN) {
        float acc[TM][TN];
        #pragma unroll
        for (int r = 0; r < TM; r++)
            #pragma unroll
            for (int c = 0; c < TN; c++) acc[r][c] = 0.f;

        for (int k0 = 0; k0 < KDIM; k0 += BK) {
            // --- load A tile [BM x BK], store transposed ---
            const float4 av = *reinterpret_cast<const float4*>(
                A + (size_t)(row0 + a_r) * KDIM + k0 + a_k);
            As[a_k + 0][a_r] = av.x;
            As[a_k + 1][a_r] = av.y;
            As[a_k + 2][a_r] = av.z;
            As[a_k + 3][a_r] = av.w;

            // --- load W tile [BK x BN] (handles dep/head split + tail) ---
            #pragma unroll
            for (int i = 0; i < 4; i++) {
                const int n = n0 + w_n + i;
                const int d = k0 + w_d;
                float v = 0.f;
                if (n < NDEP)      v = Wd[(size_t)d * NDEP + n];
                else if (n < NTOT) v = Wh[(size_t)d * NDEP + (n - NDEP)];
                Ws[w_d][w_n + i] = v;
            }
            __syncthreads();

            #pragma unroll
            for (int kk = 0; kk < BK; kk++) {
                const float4 ra = *reinterpret_cast<const float4*>(&As[kk][ty * TM]);
                const float4 rb = *reinterpret_cast<const float4*>(&Ws[kk][tx * TN]);
                const float a0 = ra.x, a1 = ra.y, a2 = ra.z, a3 = ra.w;
                const float b0 = rb.x, b1 = rb.y, b2 = rb.z, b3 = rb.w;
                acc[0][0] += a0 * b0; acc[0][1] += a0 * b1; acc[0][2] += a0 * b2; acc[0][3] += a0 * b3;
                acc[1][0] += a1 * b0; acc[1][1] += a1 * b1; acc[1][2] += a1 * b2; acc[1][3] += a1 * b3;
                acc[2][0] += a2 * b0; acc[2][1] += a2 * b1; acc[2][2] += a2 * b2; acc[2][3] += a2 * b3;
                acc[3][0] += a3 * b0; acc[3][1] += a3 * b1; acc[3][2] += a3 * b2; acc[3][3] += a3 * b3;
            }
            __syncthreads();
        }

        // --- epilogue: bias + leaky, collapse against Wc into pscore ---
        #pragma unroll
        for (int c = 0; c < TN; c++) {
            const int n = n0 + tx * TN + c;
            if (n >= NTOT) continue;
            const float bias = (n < NDEP) ? bd[n] : bh[n - NDEP];
            const float wc0  = Wc[n * 2 + 0];
            const float wc1  = Wc[n * 2 + 1];
            const int   chb  = (n < NDEP) ? 0 : 2;
            #pragma unroll
            for (int r = 0; r < TM; r++) {
                const float v  = acc[r][c] + bias;
                const float lv = (v > 0.f) ? v : NEG_SLOPE * v;
                pscore[r][chb + 0] += lv * wc0;
                pscore[r][chb + 1] += lv * wc1;
            }
        }
    }

    // --- reduce pscore across the 16 col-group lanes (width-16 segments) ---
    #pragma unroll
    for (int r = 0; r < TM; r++) {
        #pragma unroll
        for (int c = 0; c < 4; c++) {
            float v = pscore[r][c];
            #pragma unroll
            for (int off = 8; off > 0; off >>= 1)
                v += __shfl_down_sync(0xffffffffu, v, off, 16);
            if (tx == 0)
                g_scores[(size_t)(row0 + ty * TM + r) * 4 + c] = v;
        }
    }
}

// ---------------------------------------------------------------------------
// Kernel 2: out[b,i,j,c] = dep[b,i,c] + head[b,j,c] + bc[c]
// One block per (b,i) row; 256 threads x 4 j's each; float4 stores.
// ---------------------------------------------------------------------------
__global__ __launch_bounds__(256) void broadcast_kernel(
    const float* __restrict__ bc, float* __restrict__ out)
{
    const int row   = blockIdx.x;        // b*1024 + i
    const int bbase = row & ~1023;       // b*1024

    const float4 s = *reinterpret_cast<const float4*>(&g_scores[(size_t)row * 4]);
    const float d0 = s.x + bc[0];
    const float d1 = s.y + bc[1];

    float* orow = out + (size_t)row * 2048;
    const int j0 = threadIdx.x * 4;      // 4 j's per thread (256*4 = 1024)

    float4 o0, o1;
    {
        const float4 h0 = *reinterpret_cast<const float4*>(&g_scores[(size_t)(bbase + j0 + 0) * 4]);
        const float4 h1 = *reinterpret_cast<const float4*>(&g_scores[(size_t)(bbase + j0 + 1) * 4]);
        const float4 h2 = *reinterpret_cast<const float4*>(&g_scores[(size_t)(bbase + j0 + 2) * 4]);
        const float4 h3 = *reinterpret_cast<const float4*>(&g_scores[(size_t)(bbase + j0 + 3) * 4]);
        o0.x = d0 + h0.z; o0.y = d1 + h0.w;
        o0.z = d0 + h1.z; o0.w = d1 + h1.w;
        o1.x = d0 + h2.z; o1.y = d1 + h2.w;
        o1.z = d0 + h3.z; o1.w = d1 + h3.w;
    }
    *reinterpret_cast<float4*>(orow + (size_t)j0 * 2)     = o0;
    *reinterpret_cast<float4*>(orow + (size_t)j0 * 2 + 4) = o1;
}

// ---------------------------------------------------------------------------
extern "C" void kernel_launch(void* const* d_in, const int* in_sizes, int n_in,
                              void* d_out, int out_size) {
    const float* hidden = (const float*)d_in[0];
    const float* Wd     = (const float*)d_in[1];
    const float* bd     = (const float*)d_in[2];
    const float* Wh     = (const float*)d_in[3];
    const float* bh     = (const float*)d_in[4];
    const float* Wc     = (const float*)d_in[5];
    const float* bc     = (const float*)d_in[6];
    float* out = (float*)d_out;

    gemm_scores_kernel<<<R_TOTAL / BM, 256>>>(hidden, Wd, bd, Wh, bh, Wc);
    broadcast_kernel<<<R_TOTAL, 256>>>(bc, out);
}

// round 4
// speedup vs baseline: 3.9042x; 3.9042x over previous
#include <cuda_runtime.h>
#include <cuda_bf16.h>
#include <cstdint>

// ---------------- problem constants ----------------
#define R_TOTAL 16384   // B*L
#define KDIM    1024    // D
#define NDEP    500     // MLP_DIM
#define NTOT    1000
#define NPAD    1024    // padded N
#define KSTACK  3072    // [A_hi*W_hi | A_hi*W_lo | A_lo*W_hi]
#define KA      2048    // A storage: [hi | lo]
#define NEG_SLOPE 0.01f

#define BK      64      // k per stage (128 bytes bf16)
#define KITERS  (KSTACK / BK)   // 48
#define PIPE    3

// ---------------- device scratch ----------------
__device__ __nv_bfloat16 gA[(size_t)R_TOTAL * KA];   // 64 MB
__device__ __nv_bfloat16 gW[(size_t)NPAD * KSTACK];  // 6 MB (row n, K-major, zero-padded)
__device__ float g_scores[R_TOTAL * 4];              // {dep0,dep1,head0,head1} per row

// ---------------- PTX helpers ----------------
__device__ __forceinline__ uint32_t smem_u32(const void* p) {
    uint32_t a;
    asm("{ .reg .u64 t; cvta.to.shared.u64 t, %1; cvt.u32.u64 %0, t; }" : "=r"(a) : "l"(p));
    return a;
}
__device__ __forceinline__ void cp_async16(uint32_t saddr, const void* gptr) {
    asm volatile("cp.async.cg.shared.global [%0], [%1], 16;" :: "r"(saddr), "l"(gptr) : "memory");
}
#define CP_COMMIT() asm volatile("cp.async.commit_group;" ::: "memory")
#define CP_WAIT1()  asm volatile("cp.async.wait_group 1;" ::: "memory")

__device__ __forceinline__ void ldsm_x4(uint32_t* r, uint32_t addr) {
    asm volatile("ldmatrix.sync.aligned.m8n8.x4.shared.b16 {%0,%1,%2,%3}, [%4];"
        : "=r"(r[0]), "=r"(r[1]), "=r"(r[2]), "=r"(r[3]) : "r"(addr));
}
__device__ __forceinline__ void mma_bf16(float* d, const uint32_t* a, uint32_t b0, uint32_t b1) {
    asm volatile("mma.sync.aligned.m16n8k16.row.col.f32.bf16.bf16.f32 "
        "{%0,%1,%2,%3}, {%4,%5,%6,%7}, {%8,%9}, {%0,%1,%2,%3};"
        : "+f"(d[0]), "+f"(d[1]), "+f"(d[2]), "+f"(d[3])
        : "r"(a[0]), "r"(a[1]), "r"(a[2]), "r"(a[3]), "r"(b0), "r"(b1));
}

// ---------------- conversion kernels ----------------
__global__ __launch_bounds__(256) void convert_A(const float* __restrict__ A) {
    size_t idx = ((size_t)blockIdx.x * 256 + threadIdx.x) * 4;
    const float4 v = *reinterpret_cast<const float4*>(A + idx);
    const size_t m = idx >> 10, k = idx & 1023;
    float f[4] = {v.x, v.y, v.z, v.w};
    union { __nv_bfloat16 b[4]; unsigned long long u; } ph, pl;
    #pragma unroll
    for (int i = 0; i < 4; i++) {
        ph.b[i] = __float2bfloat16_rn(f[i]);
        pl.b[i] = __float2bfloat16_rn(f[i] - __bfloat162float(ph.b[i]));
    }
    *reinterpret_cast<unsigned long long*>(&gA[m * KA + k])        = ph.u;
    *reinterpret_cast<unsigned long long*>(&gA[m * KA + 1024 + k]) = pl.u;
}

__global__ __launch_bounds__(256) void convert_W(const float* __restrict__ Wd,
                                                 const float* __restrict__ Wh) {
    const int n = blockIdx.x;  // 0..1023
    for (int k = threadIdx.x; k < KDIM; k += 256) {
        float v = 0.f;
        if (n < NDEP)      v = Wd[(size_t)k * NDEP + n];
        else if (n < NTOT) v = Wh[(size_t)k * NDEP + (n - NDEP)];
        __nv_bfloat16 h = __float2bfloat16_rn(v);
        __nv_bfloat16 l = __float2bfloat16_rn(v - __bfloat162float(h));
        const size_t base = (size_t)n * KSTACK;
        gW[base + k] = h;
        gW[base + 1024 + k] = l;
        gW[base + 2048 + k] = h;
    }
}

__global__ __launch_bounds__(256) void zero_scores() {
    const int i = (blockIdx.x * 256 + threadIdx.x) * 4;
    *reinterpret_cast<float4*>(&g_scores[i]) = make_float4(0.f, 0.f, 0.f, 0.f);
}

// ---------------- mma.sync GEMM + fused scores ----------------
// grid (128 m-blocks, 8 n-blocks), 256 threads. CTA tile 128x128, K=3072 stacked.
#define S_STAGE   32768             // per-stage bytes: A 16K + B 16K
#define S_BOFF    16384
#define S_BIAS    (PIPE * S_STAGE)          // 98304
#define S_WC0     (S_BIAS + 512)
#define S_WC1     (S_WC0 + 512)
#define SMEM_TOTAL (S_WC1 + 512)            // 99840

__global__ __launch_bounds__(256, 2) void gemm_mma(const float* __restrict__ bd,
                                                   const float* __restrict__ bh,
                                                   const float* __restrict__ Wc) {
    extern __shared__ char smem[];
    const uint32_t sbase = smem_u32(smem);
    const int tid  = threadIdx.x;
    const int wid  = tid >> 5, lane = tid & 31;
    const int wm   = wid & 1,  wn   = wid >> 1;     // 2 x 4 warp grid
    const int row0 = blockIdx.x * 128;
    const int n0g  = blockIdx.y * 128;

    // bias / Wc staging for this CTA's n-range
    float* s_bias = (float*)(smem + S_BIAS);
    float* s_wc0  = (float*)(smem + S_WC0);
    float* s_wc1  = (float*)(smem + S_WC1);
    if (tid < 128) {
        const int n = n0g + tid;
        float b = 0.f, w0 = 0.f, w1 = 0.f;
        if (n < NDEP)      b = bd[n];
        else if (n < NTOT) b = bh[n - NDEP];
        if (n < NTOT) { w0 = Wc[n * 2]; w1 = Wc[n * 2 + 1]; }
        s_bias[tid] = b; s_wc0[tid] = w0; s_wc1[tid] = w1;
    }

    const char* Abase = (const char*)gA + (size_t)row0 * (KA * 2);
    const char* Bbase = (const char*)gW + (size_t)n0g * (KSTACK * 2);

    // issue loads for one stage: kit -> stacked kg, A-plane remap
    auto issue_stage = [&](int kit, int stg) {
        const int kg = kit * BK;
        const int ka = (kg < 1024) ? kg : kg - 1024;
        const uint32_t sa = sbase + stg * S_STAGE;
        const uint32_t sb = sa + S_BOFF;
        const char* ag = Abase + (size_t)ka * 2;
        const char* bg = Bbase + (size_t)kg * 2;
        #pragma unroll
        for (int i = 0; i < 4; i++) {
            const int seg = tid + i * 256;            // 0..1023
            const int r = seg >> 3, s = seg & 7;
            const uint32_t off = (uint32_t)r * 128u + ((uint32_t)(s * 16) ^ (((uint32_t)r & 7u) << 4));
            cp_async16(sa + off, ag + (size_t)r * (KA * 2) + s * 16);
            cp_async16(sb + off, bg + (size_t)r * (KSTACK * 2) + s * 16);
        }
    };

    // prologue
    issue_stage(0, 0); CP_COMMIT();
    issue_stage(1, 1); CP_COMMIT();

    float acc[4][4][4];
    #pragma unroll
    for (int mi = 0; mi < 4; mi++)
        #pragma unroll
        for (int nj = 0; nj < 4; nj++)
            #pragma unroll
            for (int c = 0; c < 4; c++) acc[mi][nj][c] = 0.f;

    const int lane15 = lane & 15;
    const int laneh  = lane >> 4;
    const uint32_t xm = ((uint32_t)lane & 7u) << 4;
    uint32_t a_row[4], b_row[2];
    #pragma unroll
    for (int mi = 0; mi < 4; mi++) a_row[mi] = (uint32_t)(wm * 64 + mi * 16 + lane15) * 128u;
    #pragma unroll
    for (int ni = 0; ni < 2; ni++) b_row[ni] = (uint32_t)(wn * 32 + ni * 16 + lane15) * 128u;

    #pragma unroll 1
    for (int kit = 0; kit < KITERS; kit++) {
        CP_WAIT1();
        __syncthreads();
        const int pf = kit + 2;
        if (pf < KITERS) issue_stage(pf, pf % PIPE);
        CP_COMMIT();

        const uint32_t sa = sbase + (kit % PIPE) * S_STAGE;
        const uint32_t sb = sa + S_BOFF;

        #pragma unroll
        for (int kk = 0; kk < 4; kk++) {
            const uint32_t cc = ((uint32_t)(kk * 32 + laneh * 16)) ^ xm;
            uint32_t a[4][4], b[2][4];
            #pragma unroll
            for (int mi = 0; mi < 4; mi++) ldsm_x4(a[mi], sa + a_row[mi] + cc);
            #pragma unroll
            for (int ni = 0; ni < 2; ni++) ldsm_x4(b[ni], sb + b_row[ni] + cc);
            #pragma unroll
            for (int mi = 0; mi < 4; mi++) {
                #pragma unroll
                for (int nj = 0; nj < 4; nj++) {
                    const int ni2 = nj >> 1, w = nj & 1;
                    mma_bf16(acc[mi][nj], a[mi], b[ni2][w], b[ni2][w + 2]);
                }
            }
        }
    }

    // ---- epilogue: bias + leaky + Wc collapse, lane reduce, atomic scores ----
    float p[4][2][4];
    #pragma unroll
    for (int mi = 0; mi < 4; mi++)
        #pragma unroll
        for (int h = 0; h < 2; h++)
            #pragma unroll
            for (int j = 0; j < 4; j++) p[mi][h][j] = 0.f;

    #pragma unroll
    for (int mi = 0; mi < 4; mi++) {
        #pragma unroll
        for (int nj = 0; nj < 4; nj++) {
            #pragma unroll
            for (int c = 0; c < 4; c++) {
                const int h = c >> 1, e = c & 1;
                const int nloc = wn * 32 + nj * 8 + (lane & 3) * 2 + e;
                const int n = n0g + nloc;
                const float v  = acc[mi][nj][c] + s_bias[nloc];
                const float lv = (v > 0.f) ? v : NEG_SLOPE * v;
                const int idx = (n < NDEP) ? 0 : 2;
                p[mi][h][idx]     += lv * s_wc0[nloc];
                p[mi][h][idx + 1] += lv * s_wc1[nloc];
            }
        }
    }

    #pragma unroll
    for (int mi = 0; mi < 4; mi++) {
        #pragma unroll
        for (int h = 0; h < 2; h++) {
            const int row = row0 + wm * 64 + mi * 16 + (lane >> 2) + 8 * h;
            #pragma unroll
            for (int j = 0; j < 4; j++) {
                float v = p[mi][h][j];
                v += __shfl_xor_sync(0xffffffffu, v, 1);
                v += __shfl_xor_sync(0xffffffffu, v, 2);
                if ((lane & 3) == 0) atomicAdd(&g_scores[(size_t)row * 4 + j], v);
            }
        }
    }
}

// ---------------- broadcast ----------------
__global__ __launch_bounds__(256) void broadcast_kernel(const float* __restrict__ bc,
                                                        float* __restrict__ out) {
    const int row   = blockIdx.x;
    const int bbase = row & ~1023;

    const float4 s = *reinterpret_cast<const float4*>(&g_scores[(size_t)row * 4]);
    const float d0 = s.x + bc[0];
    const float d1 = s.y + bc[1];

    float* orow = out + (size_t)row * 2048;
    const int j0 = threadIdx.x * 4;

    const float4 h0 = *reinterpret_cast<const float4*>(&g_scores[(size_t)(bbase + j0 + 0) * 4]);
    const float4 h1 = *reinterpret_cast<const float4*>(&g_scores[(size_t)(bbase + j0 + 1) * 4]);
    const float4 h2 = *reinterpret_cast<const float4*>(&g_scores[(size_t)(bbase + j0 + 2) * 4]);
    const float4 h3 = *reinterpret_cast<const float4*>(&g_scores[(size_t)(bbase + j0 + 3) * 4]);
    float4 o0, o1;
    o0.x = d0 + h0.z; o0.y = d1 + h0.w;
    o0.z = d0 + h1.z; o0.w = d1 + h1.w;
    o1.x = d0 + h2.z; o1.y = d1 + h2.w;
    o1.z = d0 + h3.z; o1.w = d1 + h3.w;
    *reinterpret_cast<float4*>(orow + (size_t)j0 * 2)     = o0;
    *reinterpret_cast<float4*>(orow + (size_t)j0 * 2 + 4) = o1;
}

// ---------------- launch ----------------
extern "C" void kernel_launch(void* const* d_in, const int* in_sizes, int n_in,
                              void* d_out, int out_size) {
    const float* hidden = (const float*)d_in[0];
    const float* Wd     = (const float*)d_in[1];
    const float* bd     = (const float*)d_in[2];
    const float* Wh     = (const float*)d_in[3];
    const float* bh     = (const float*)d_in[4];
    const float* Wc     = (const float*)d_in[5];
    const float* bc     = (const float*)d_in[6];
    float* out = (float*)d_out;

    cudaFuncSetAttribute(gemm_mma, cudaFuncAttributeMaxDynamicSharedMemorySize, SMEM_TOTAL);

    convert_A<<<(R_TOTAL * KDIM) / (256 * 4), 256>>>(hidden);
    convert_W<<<NPAD, 256>>>(Wd, Wh);
    zero_scores<<<R_TOTAL * 4 / 1024, 256>>>();
    gemm_mma<<<dim3(R_TOTAL / 128, NPAD / 128), 256, SMEM_TOTAL>>>(bd, bh, Wc);
    broadcast_kernel<<<R_TOTAL, 256>>>(bc, out);
}